// round 3
// baseline (speedup 1.0000x reference)
#include <cuda_runtime.h>
#include <math.h>
#include <stdint.h>

// ---------------------------------------------------------------------------
// Problem constants
// ---------------------------------------------------------------------------
#define BATCH 8
#define CCH   384        // channels
#define HH    56
#define WW    56
#define NTOK  (BATCH*HH*WW)   // 25088 tokens
#define QKVC  (3*CCH)         // 1152
#define HIDN  1536
#define NHEAD 12
#define HDIM  32
#define EPSLN 1e-5f

// ---------------------------------------------------------------------------
// Scratch (static device globals: no allocation at kernel_launch time)
// ---------------------------------------------------------------------------
__device__ float g_xn [(size_t)NTOK*CCH];   // LN1 output, token-major [N,C]
__device__ float g_xpT[(size_t)NTOK*CCH];   // raw transposed x, [N,C]
__device__ float g_qkv[(size_t)NTOK*QKVC];  // [N,1152]
__device__ float g_att[(size_t)NTOK*CCH];   // attention out + xn residual
__device__ float g_xpb[(size_t)NTOK*CCH];   // after proj residual
__device__ float g_x2 [(size_t)NTOK*CCH];   // LN2 output
__device__ float g_h  [(size_t)NTOK*HIDN];  // MLP hidden
__device__ float g_xf [(size_t)NTOK*CCH];   // final token-major result

// ---------------------------------------------------------------------------
// LN1: x [B,C,H,W] -> xn [N,C] (normed) and xpT [N,C] (raw transpose)
// One block handles 28 consecutive-x tokens of one (b,y) row. grid (2,56,8).
// ---------------------------------------------------------------------------
__global__ __launch_bounds__(256) void ln1_kernel(
    const float* __restrict__ x, const float* __restrict__ gam,
    const float* __restrict__ bet, float* __restrict__ xn,
    float* __restrict__ xpT)
{
    const int TPB = 28;                 // tokens per block
    __shared__ float s[CCH*TPB];        // [c][t], 43008 B
    __shared__ float ps[9*TPB];
    __shared__ float pq[9*TPB];
    __shared__ float s_mean[TPB];
    __shared__ float s_rstd[TPB];

    int tid = threadIdx.x;
    int x0  = blockIdx.x * TPB;
    int y   = blockIdx.y;
    int b   = blockIdx.z;

    // coalesced load: consecutive tid -> consecutive x column
    for (int idx = tid; idx < CCH*TPB; idx += 256) {
        int c = idx / TPB;
        int t = idx % TPB;
        s[idx] = x[(((size_t)b*CCH + c)*HH + y)*WW + x0 + t];
    }
    __syncthreads();

    if (tid < 9*TPB) {
        int sub = tid / TPB;   // 0..8
        int t   = tid % TPB;
        float sm = 0.f, sq = 0.f;
        for (int c = sub; c < CCH; c += 9) {
            float v = s[c*TPB + t];
            sm += v; sq += v*v;
        }
        ps[sub*TPB + t] = sm;
        pq[sub*TPB + t] = sq;
    }
    __syncthreads();
    if (tid < TPB) {
        float sm = 0.f, sq = 0.f;
        #pragma unroll
        for (int sub = 0; sub < 9; sub++) { sm += ps[sub*TPB + tid]; sq += pq[sub*TPB + tid]; }
        float mu  = sm * (1.f/CCH);
        float var = sq * (1.f/CCH) - mu*mu;
        s_mean[tid] = mu;
        s_rstd[tid] = rsqrtf(var + EPSLN);
    }
    __syncthreads();

    // coalesced writes: idx = t*C + c, consecutive c contiguous in [N,C]
    for (int idx = tid; idx < CCH*TPB; idx += 256) {
        int t = idx / CCH;
        int c = idx % CCH;
        float v = s[c*TPB + t];
        size_t n = (size_t)b*(HH*WW) + (size_t)y*WW + (x0 + t);
        xpT[n*CCH + c] = v;
        xn [n*CCH + c] = (v - s_mean[t]) * s_rstd[t] * gam[c] + bet[c];
    }
}

// ---------------------------------------------------------------------------
// Generic fp32 GEMM:  C[M,Nc] = A[M,K] @ Bw[Nc,K]^T  (+bias)(+gelu|+residual)
// BM=BN=128, BK=16, 256 threads, 8x8 register tile per thread.
// mode: 0 = bias-only(if bias), 1 = bias+exact GELU, 2 = bias+residual
// M % 128 == 0, Nc % 128 == 0, K % 16 == 0 guaranteed by the shapes here.
// ---------------------------------------------------------------------------
__global__ __launch_bounds__(256) void gemm_nt_kernel(
    const float* __restrict__ A, const float* __restrict__ Bw,
    const float* __restrict__ bias, const float* __restrict__ resid,
    float* __restrict__ C, int M, int Nc, int K, int mode)
{
    const int BM = 128, BN = 128, BK = 16;
    __shared__ float As[BK][BM];
    __shared__ float Bs[BK][BN];

    int tid = threadIdx.x;
    int m0 = blockIdx.x * BM;
    int n0 = blockIdx.y * BN;
    int tr = tid >> 4;   // 0..15 (M direction)
    int tc = tid & 15;   // 0..15 (N direction)

    const float* Aptr = A  + (size_t)m0 * K;
    const float* Bptr = Bw + (size_t)n0 * K;

    float acc[8][8];
    #pragma unroll
    for (int i = 0; i < 8; i++)
        #pragma unroll
        for (int j = 0; j < 8; j++) acc[i][j] = 0.f;

    for (int k0 = 0; k0 < K; k0 += BK) {
        // 128 rows x 16 k = 512 float4 for each of A and B tiles
        #pragma unroll
        for (int it = 0; it < 2; it++) {
            int f   = tid + it * 256;      // 0..511
            int row = f >> 2;
            int kc  = (f & 3) << 2;
            float4 va = *(const float4*)(Aptr + (size_t)row * K + k0 + kc);
            As[kc+0][row] = va.x; As[kc+1][row] = va.y;
            As[kc+2][row] = va.z; As[kc+3][row] = va.w;
            float4 vb = *(const float4*)(Bptr + (size_t)row * K + k0 + kc);
            Bs[kc+0][row] = vb.x; Bs[kc+1][row] = vb.y;
            Bs[kc+2][row] = vb.z; Bs[kc+3][row] = vb.w;
        }
        __syncthreads();

        #pragma unroll
        for (int k = 0; k < BK; k++) {
            float a[8], b[8];
            *(float4*)&a[0] = *(const float4*)&As[k][tr*8];
            *(float4*)&a[4] = *(const float4*)&As[k][tr*8 + 4];
            *(float4*)&b[0] = *(const float4*)&Bs[k][tc*8];
            *(float4*)&b[4] = *(const float4*)&Bs[k][tc*8 + 4];
            #pragma unroll
            for (int i = 0; i < 8; i++)
                #pragma unroll
                for (int j = 0; j < 8; j++)
                    acc[i][j] = fmaf(a[i], b[j], acc[i][j]);
        }
        __syncthreads();
    }

    #pragma unroll
    for (int i = 0; i < 8; i++) {
        size_t m = (size_t)m0 + tr*8 + i;
        #pragma unroll
        for (int j = 0; j < 8; j++) {
            int n = n0 + tc*8 + j;
            float v = acc[i][j];
            if (bias) v += bias[n];
            if (mode == 1) {
                // exact GELU (erf form), matches jax approximate=False
                v = 0.5f * v * (1.0f + erff(v * 0.7071067811865476f));
            } else if (mode == 2) {
                v += resid[m * Nc + n];
            }
            C[m * Nc + n] = v;
        }
    }
}

// ---------------------------------------------------------------------------
// Multi-dilation 3x3 local attention. One block per token, one warp per head.
// OOB neighbors contribute logit exactly 0 (zero-padded unfold) and v = 0.
// Output: att[n,c] = attn_out + xn[n,c]   (fused "a = a + xn" residual)
// ---------------------------------------------------------------------------
__global__ __launch_bounds__(384) void attn_kernel(
    const float* __restrict__ qkv, const float* __restrict__ xn,
    float* __restrict__ att)
{
    int n    = blockIdx.x;
    int b    = n / (HH*WW);
    int rem  = n % (HH*WW);
    int y    = rem / WW;
    int xx   = rem % WW;
    int w    = threadIdx.x >> 5;      // head 0..11
    int lane = threadIdx.x & 31;      // dim within head

    int dil = (w >> 2) + 1;           // DILS = (1,2,3)
    int c0  = w * HDIM;               // = branch*128 + head_in_branch*32

    const float scale = 0.17677669529663687f;   // 32^-0.5

    float q = qkv[(size_t)n*QKVC + c0 + lane];

    float logit[9];
    int   nn[9];
    #pragma unroll
    for (int e = 0; e < 9; e++) {
        int ki = e / 3, kj = e % 3;
        int ny = y  + (ki - 1) * dil;
        int nx = xx + (kj - 1) * dil;
        bool ok = ((unsigned)ny < HH) && ((unsigned)nx < WW);
        int tok = ok ? (b*(HH*WW) + ny*WW + nx) : -1;
        nn[e] = tok;
        float p = 0.f;
        if (ok) p = q * qkv[(size_t)tok*QKVC + CCH + c0 + lane];
        #pragma unroll
        for (int off = 16; off > 0; off >>= 1)
            p += __shfl_xor_sync(0xffffffffu, p, off);
        logit[e] = p * scale;         // OOB -> exactly 0, still in softmax
    }

    float mx = logit[0];
    #pragma unroll
    for (int e = 1; e < 9; e++) mx = fmaxf(mx, logit[e]);
    float pe[9];
    float sum = 0.f;
    #pragma unroll
    for (int e = 0; e < 9; e++) { pe[e] = __expf(logit[e] - mx); sum += pe[e]; }
    float inv = 1.f / sum;

    float o = 0.f;
    #pragma unroll
    for (int e = 0; e < 9; e++) {
        if (nn[e] >= 0)
            o = fmaf(pe[e] * inv,
                     qkv[(size_t)nn[e]*QKVC + 2*CCH + c0 + lane], o);
    }

    att[(size_t)n*CCH + c0 + lane] = o + xn[(size_t)n*CCH + c0 + lane];
}

// ---------------------------------------------------------------------------
// LN2 over token-major [N,C]. One block (128 threads) per token.
// ---------------------------------------------------------------------------
__global__ __launch_bounds__(128) void ln2_kernel(
    const float* __restrict__ in, const float* __restrict__ gam,
    const float* __restrict__ bet, float* __restrict__ out)
{
    __shared__ float rs[4], rq[4];
    __shared__ float s_mu, s_rstd;
    int n   = blockIdx.x;
    int tid = threadIdx.x;
    const float* row = in + (size_t)n * CCH;

    float v0 = row[tid];
    float v1 = row[tid + 128];
    float v2 = row[tid + 256];
    float sm = v0 + v1 + v2;
    float sq = v0*v0 + v1*v1 + v2*v2;
    #pragma unroll
    for (int off = 16; off > 0; off >>= 1) {
        sm += __shfl_xor_sync(0xffffffffu, sm, off);
        sq += __shfl_xor_sync(0xffffffffu, sq, off);
    }
    int wid = tid >> 5, lane = tid & 31;
    if (lane == 0) { rs[wid] = sm; rq[wid] = sq; }
    __syncthreads();
    if (tid == 0) {
        float tsm = rs[0]+rs[1]+rs[2]+rs[3];
        float tsq = rq[0]+rq[1]+rq[2]+rq[3];
        float mu  = tsm * (1.f/CCH);
        float var = tsq * (1.f/CCH) - mu*mu;
        s_mu = mu;
        s_rstd = rsqrtf(var + EPSLN);
    }
    __syncthreads();
    float mu = s_mu, rstd = s_rstd;
    float* orow = out + (size_t)n * CCH;
    orow[tid      ] = (v0 - mu) * rstd * gam[tid      ] + bet[tid      ];
    orow[tid + 128] = (v1 - mu) * rstd * gam[tid + 128] + bet[tid + 128];
    orow[tid + 256] = (v2 - mu) * rstd * gam[tid + 256] + bet[tid + 256];
}

// ---------------------------------------------------------------------------
// Final transpose: [B, HW, C] -> [B, C, HW]  (32x32 tiles through shared)
// ---------------------------------------------------------------------------
__global__ __launch_bounds__(256) void transpose_out_kernel(
    const float* __restrict__ in, float* __restrict__ out)
{
    __shared__ float tile[32][33];
    int b  = blockIdx.z;
    int c0 = blockIdx.x * 32;   // channel tile
    int s0 = blockIdx.y * 32;   // spatial tile
    int tx = threadIdx.x;       // 0..31
    int ty = threadIdx.y;       // 0..7

    #pragma unroll
    for (int rr = ty; rr < 32; rr += 8)
        tile[rr][tx] = in[((size_t)b*(HH*WW) + s0 + rr)*CCH + c0 + tx];
    __syncthreads();
    #pragma unroll
    for (int rr = ty; rr < 32; rr += 8)
        out[((size_t)b*CCH + c0 + rr)*(HH*WW) + s0 + tx] = tile[tx][rr];
}

// ---------------------------------------------------------------------------
// kernel_launch
// ---------------------------------------------------------------------------
extern "C" void kernel_launch(void* const* d_in, const int* in_sizes, int n_in,
                              void* d_out, int out_size)
{
    const float* x      = (const float*)d_in[0];
    const float* qkv_w  = (const float*)d_in[1];
    const float* proj_w = (const float*)d_in[2];
    const float* proj_b = (const float*)d_in[3];
    const float* n1_g   = (const float*)d_in[4];
    const float* n1_b   = (const float*)d_in[5];
    const float* n2_g   = (const float*)d_in[6];
    const float* n2_b   = (const float*)d_in[7];
    const float* fc1_w  = (const float*)d_in[8];
    const float* fc1_b  = (const float*)d_in[9];
    const float* fc2_w  = (const float*)d_in[10];
    const float* fc2_b  = (const float*)d_in[11];
    float* out = (float*)d_out;

    float *xn, *xpT, *qkv, *att, *xpb, *x2, *h, *xf;
    cudaGetSymbolAddress((void**)&xn,  g_xn);
    cudaGetSymbolAddress((void**)&xpT, g_xpT);
    cudaGetSymbolAddress((void**)&qkv, g_qkv);
    cudaGetSymbolAddress((void**)&att, g_att);
    cudaGetSymbolAddress((void**)&xpb, g_xpb);
    cudaGetSymbolAddress((void**)&x2,  g_x2);
    cudaGetSymbolAddress((void**)&h,   g_h);
    cudaGetSymbolAddress((void**)&xf,  g_xf);

    // 1. LN1 + NCHW->NHWC transpose
    ln1_kernel<<<dim3(2, HH, BATCH), 256>>>(x, n1_g, n1_b, xn, xpT);

    // 2. QKV 1x1 conv: [N,384] @ [1152,384]^T, no bias
    gemm_nt_kernel<<<dim3(NTOK/128, QKVC/128), 256>>>(
        xn, qkv_w, nullptr, nullptr, qkv, NTOK, QKVC, CCH, 0);

    // 3. Multi-dilation local attention + xn residual
    attn_kernel<<<NTOK, 384>>>(qkv, xn, att);

    // 4. proj + bias + residual(raw transposed x)
    gemm_nt_kernel<<<dim3(NTOK/128, CCH/128), 256>>>(
        att, proj_w, proj_b, xpT, xpb, NTOK, CCH, CCH, 2);

    // 5. LN2
    ln2_kernel<<<NTOK, 128>>>(xpb, n2_g, n2_b, x2);

    // 6. fc1 + bias + exact GELU
    gemm_nt_kernel<<<dim3(NTOK/128, HIDN/128), 256>>>(
        x2, fc1_w, fc1_b, nullptr, h, NTOK, HIDN, CCH, 1);

    // 7. fc2 + bias + residual
    gemm_nt_kernel<<<dim3(NTOK/128, CCH/128), 256>>>(
        h, fc2_w, fc2_b, xpb, xf, NTOK, CCH, HIDN, 2);

    // 8. NHWC -> NCHW
    transpose_out_kernel<<<dim3(CCH/32, (HH*WW)/32, BATCH), dim3(32, 8)>>>(xf, out);
}